// round 9
// baseline (speedup 1.0000x reference)
#include <cuda_runtime.h>
#include <cuda_fp16.h>

// FernSparseTable v7: half-table pipelined fills + predicated two-pass gathers.
//  Table rows [0,512) / [512,1024) are 64 KB chunks with separate mbarriers.
//  Pass p gathers only probes whose row bit9 == p (explicit-predicate PTX body),
//  so fill(m+1, chunk) overlaps the opposite pass of fern m. Fill exposure ~0.

#define TPB 512
#define NPX 131072
#define NCTA 296
#define PX_PER 443                   // ceil(131072/296); last CTA gets 387
#define TAB_BYTES 131072             // 1024 rows * 128 B
#define HALF_TAB 65536
#define PAR_STRIDE 80                // 8 probes * 8B + 16B pad
#define MBAR_OFF  (TAB_BYTES + TPB * PAR_STRIDE)   // 172032
#define SMEM_BYTES (MBAR_OFF + 16)                 // 172048

__device__ __align__(128) __half g_W16[16 * 1024 * 64];

__global__ void cvt_kernel(const float4* __restrict__ W)
{
    int i = blockIdx.x * blockDim.x + threadIdx.x;   // 262144 float4
    float4 v = W[i];
    __half2 a = __floats2half2_rn(v.x, v.y);
    __half2 b = __floats2half2_rn(v.z, v.w);
    uint2 r;
    r.x = *reinterpret_cast<unsigned*>(&a);
    r.y = *reinterpret_cast<unsigned*>(&b);
    reinterpret_cast<uint2*>(g_W16)[i] = r;
}

__device__ __forceinline__ __half2 u2h2(unsigned u) {
    return *reinterpret_cast<__half2*>(&u);
}

extern __shared__ char smem_raw[];

__device__ __forceinline__ void mbar_wait(unsigned mbar, unsigned parity)
{
    unsigned done;
    asm volatile(
        "{\n\t.reg .pred p;\n\t"
        "mbarrier.try_wait.parity.acquire.cta.shared::cta.b64 p, [%1], %2;\n\t"
        "selp.b32 %0, 1, 0, p;\n\t}"
        : "=r"(done) : "r"(mbar), "r"(parity) : "memory");
    if (!done) {
        asm volatile(
            "{\n\t.reg .pred P1;\n\t"
            "WL_%=:\n\t"
            "mbarrier.try_wait.parity.acquire.cta.shared::cta.b64 P1, [%0], %1, 0x989680;\n\t"
            "@P1 bra.uni WD_%=;\n\t"
            "bra.uni WL_%=;\n\t"
            "WD_%=:\n\t}"
            :: "r"(mbar), "r"(parity) : "memory");
    }
}

// Predicated gather-probe: executes iff actdiff == 0. Always 6 issue slots,
// crossbar/fma only when active. h0..h3 are packed half2 accumulators.
__device__ __forceinline__ void probe_pred(unsigned &h0, unsigned &h1,
                                           unsigned &h2, unsigned &h3,
                                           unsigned c, unsigned addr,
                                           unsigned actdiff)
{
    asm volatile(
        "{\n\t"
        ".reg .pred p;\n\t"
        ".reg .b32 w0, w1, w2, w3;\n\t"
        "setp.eq.u32 p, %6, 0;\n\t"
        "@p ld.shared.v4.b32 {w0, w1, w2, w3}, [%5];\n\t"
        "@p fma.rn.f16x2 %0, %4, w0, %0;\n\t"
        "@p fma.rn.f16x2 %1, %4, w1, %1;\n\t"
        "@p fma.rn.f16x2 %2, %4, w2, %2;\n\t"
        "@p fma.rn.f16x2 %3, %4, w3, %3;\n\t"
        "}"
        : "+r"(h0), "+r"(h1), "+r"(h2), "+r"(h3)
        : "r"(c), "r"(addr), "r"(actdiff));
}

__global__ __launch_bounds__(TPB, 1)
void fern_kernel(const float* __restrict__ B,
                 const float* __restrict__ bias,
                 float* __restrict__ out)
{
    char*  s_par = smem_raw + TAB_BYTES;
    float* s_out = (float*)smem_raw;         // epilogue reuse

    const int tid  = threadIdx.x;
    const int lane = tid & 31;
    const int warp = tid >> 5;

    const int base = blockIdx.x * PX_PER;
    const int cnt  = min(PX_PER, NPX - base);       // 443 or 387
    const int px   = min(base + tid, NPX - 1);      // clamped pixel id
    const bool valid = (base + tid) < NPX && tid < cnt;
    const int n  = px >> 12;
    const int hw = px & 4095;
    const int rem = cnt - warp * 32;                // per-warp tail bound

    unsigned smem_u32 = (unsigned)__cvta_generic_to_shared(smem_raw);
    const unsigned mb_lo = smem_u32 + MBAR_OFF;
    const unsigned mb_hi = mb_lo + 8;

    if (tid == 0) {
        asm volatile("mbarrier.init.shared.b64 [%0], 1;" :: "r"(mb_lo) : "memory");
        asm volatile("mbarrier.init.shared.b64 [%0], 1;" :: "r"(mb_hi) : "memory");
        asm volatile("fence.proxy.async.shared::cta;" ::: "memory");
    }

    const float* Bb = B + (n * 160) * 4096 + hw;
    const unsigned long long Wg =
        (unsigned long long)__cvta_generic_to_global(g_W16);

    float acc[64];
    #pragma unroll
    for (int i = 0; i < 64; ++i) acc[i] = 0.f;

    const unsigned gl_u32 = smem_u32 + (lane & 7) * 16;  // lane's 16B d-slice
    const int px_sub = lane >> 3;                        // 0..3

    // issue one 64 KB half-fill (tid 0 only)
    auto issue_fill = [&](int m, int h) {
        const unsigned mb = h ? mb_hi : mb_lo;
        asm volatile("mbarrier.arrive.expect_tx.shared.b64 _, [%0], %1;"
                     :: "r"(mb), "r"(HALF_TAB) : "memory");
        unsigned long long src =
            Wg + (unsigned long long)m * 131072ull + (unsigned long long)h * HALF_TAB;
        unsigned dst = smem_u32 + h * HALF_TAB;
        #pragma unroll
        for (int c = 0; c < 2; ++c) {
            asm volatile(
                "cp.async.bulk.shared::cta.global.mbarrier::complete_tx::bytes "
                "[%0], [%1], %2, [%3];"
                :: "r"(dst + c * 32768), "l"(src + c * 32768ull),
                   "r"(32768), "r"(mb) : "memory");
        }
    };

    // phase-1: fern logic -> packed params in smem (warp-local consumption)
    auto phase1 = [&](const float* tv) {
        int wb = 0;
        float bsp = 1.f;
        #pragma unroll
        for (int k = 0; k < 10; ++k) {
            if (tv[k] >= 0.5f) wb |= (1 << k);
            bsp *= fmaxf(tv[k], 1.f - tv[k]);
        }
        int abi0, abi1, abi2;
        float av0, av1, av2;
        {
            float best = fabsf(tv[0] - 0.5f); int bi = 0; float bt = tv[0];
            #pragma unroll
            for (int k = 1; k < 10; ++k) {
                float ak = fabsf(tv[k] - 0.5f);
                if (ak < best) { best = ak; bi = k; bt = tv[k]; }
            }
            abi0 = bi; av0 = bt;
        }
        {
            float best = 3.0e38f; int bi = 0; float bt = 0.f;
            #pragma unroll
            for (int k = 0; k < 10; ++k) {
                float ak = fabsf(tv[k] - 0.5f);
                if (k != abi0 && ak < best) { best = ak; bi = k; bt = tv[k]; }
            }
            abi1 = bi; av1 = bt;
        }
        {
            float best = 3.0e38f; int bi = 0; float bt = 0.f;
            #pragma unroll
            for (int k = 0; k < 10; ++k) {
                float ak = fabsf(tv[k] - 0.5f);
                if (k != abi0 && k != abi1 && ak < best) { best = ak; bi = k; bt = tv[k]; }
            }
            abi2 = bi; av2 = bt;
        }

        const float d0 = 1.f - av0, d1 = 1.f - av1, d2 = 1.f - av2;
        const float denom = fmaxf(av0, d0) * fmaxf(av1, d1) * fmaxf(av2, d2);
        const float bspp = valid ? (bsp / denom) : 0.f;

        float cp[8];
        {
            float g0 = bspp * d0,  g1 = bspp * av0;
            float c00 = g0 * d1,  c10 = g1 * d1;
            float c01 = g0 * av1, c11 = g1 * av1;
            cp[0] = c00 * d2;  cp[1] = c10 * d2;  cp[2] = c01 * d2;  cp[3] = c11 * d2;
            cp[4] = c00 * av2; cp[5] = c10 * av2; cp[6] = c01 * av2; cp[7] = c11 * av2;
        }
        unsigned ch[8];
        #pragma unroll
        for (int j = 0; j < 8; ++j) {
            __half2 hh = __floats2half2_rn(cp[j], cp[j]);
            ch[j] = *reinterpret_cast<unsigned*>(&hh);
        }
        int io[8];
        {
            const int m0 = 1 << abi0, m1 = 1 << abi1, m2 = 1 << abi2;
            const int b0 = wb & ~(m0 | m1 | m2);
            const int i0 = b0, i1 = b0 | m0, i2 = b0 | m1, i3 = b0 | m0 | m1;
            io[0] = i0 << 7;        io[1] = i1 << 7;
            io[2] = i2 << 7;        io[3] = i3 << 7;
            io[4] = (i0 | m2) << 7; io[5] = (i1 | m2) << 7;
            io[6] = (i2 | m2) << 7; io[7] = (i3 | m2) << 7;
        }
        uint4* myp = (uint4*)(s_par + tid * PAR_STRIDE);
        #pragma unroll
        for (int jj = 0; jj < 4; ++jj)
            myp[jj] = make_uint4(ch[2*jj], (unsigned)io[2*jj],
                                 ch[2*jj+1], (unsigned)io[2*jj+1]);
        __syncwarp();
    };

    // ---- prologue ----
    float tc[10], tn[10];
    #pragma unroll
    for (int k = 0; k < 10; ++k) tc[k] = Bb[k * 4096];
    {
        const float* pf = Bb + 40960;
        #pragma unroll
        for (int k = 0; k < 10; ++k) tn[k] = pf[k * 4096];
    }
    phase1(tc);
    __syncthreads();            // mbar init visible before any wait
    if (tid == 0) { issue_fill(0, 0); issue_fill(0, 1); }

    #pragma unroll 1
    for (int m = 0; m < 16; ++m) {
        const unsigned parity = (unsigned)(m & 1);
        float t2[10];

        #pragma unroll
        for (int pass = 0; pass < 2; ++pass) {
            mbar_wait(pass ? mb_hi : mb_lo, parity);

            // gather pass: probes whose row bit9 == pass
            #pragma unroll
            for (int g = 0; g < 8; ++g) {
                if (g * 4 < rem) {            // warp-uniform tail guard
                    const uint4* pp =
                        (const uint4*)(s_par + (warp * 32 + g * 4 + px_sub) * PAR_STRIDE);
                    unsigned h0 = 0, h1 = 0, h2 = 0, h3 = 0;
                    #pragma unroll
                    for (int jj = 0; jj < 4; ++jj) {
                        uint4 pr = pp[jj];
                        probe_pred(h0, h1, h2, h3, pr.x, gl_u32 + pr.y,
                                   (pr.y >> 16) ^ (unsigned)pass);
                        probe_pred(h0, h1, h2, h3, pr.z, gl_u32 + pr.w,
                                   (pr.w >> 16) ^ (unsigned)pass);
                    }
                    float2 f0 = __half22float2(u2h2(h0));
                    float2 f1 = __half22float2(u2h2(h1));
                    float2 f2 = __half22float2(u2h2(h2));
                    float2 f3 = __half22float2(u2h2(h3));
                    acc[g*8+0] += f0.x; acc[g*8+1] += f0.y;
                    acc[g*8+2] += f1.x; acc[g*8+3] += f1.y;
                    acc[g*8+4] += f2.x; acc[g*8+5] += f2.y;
                    acc[g*8+6] += f3.x; acc[g*8+7] += f3.y;
                }
            }

            if (m < 15) {
                // gate: all warps done with this chunk -> warp0 refills it
                if (warp == 0) {
                    if (pass == 0) asm volatile("bar.sync 1, 512;" ::: "memory");
                    else           asm volatile("bar.sync 2, 512;" ::: "memory");
                    if (tid == 0) issue_fill(m + 1, pass);
                } else {
                    if (pass == 0) asm volatile("bar.arrive 1, 512;" ::: "memory");
                    else           asm volatile("bar.arrive 2, 512;" ::: "memory");
                }
            }

            if (pass == 0) {
                // prefetch B for fern m+2 between the two passes
                const int mn = (m + 2 < 16) ? (m + 2) : 15;
                const float* pf = Bb + mn * 40960;
                #pragma unroll
                for (int k = 0; k < 10; ++k) t2[k] = pf[k * 4096];
            }
        }

        if (m < 15) {
            phase1(tn);           // fern m+1 params (own pixels only)
            #pragma unroll
            for (int k = 0; k < 10; ++k) tn[k] = t2[k];
        }
    }

    // ---- epilogue: stride-65 transpose -> coalesced stores ----
    __syncthreads();
    #pragma unroll
    for (int g = 0; g < 8; ++g) {
        int pxl = warp * 32 + g * 4 + px_sub;
        float* row = s_out + pxl * 65 + (lane & 7) * 8;
        #pragma unroll
        for (int r = 0; r < 8; ++r) row[r] = acc[g * 8 + r];
    }
    __syncthreads();

    if (valid) {
        const float* srow = s_out + tid * 65;
        float* obase = out + (n * 64) * 4096 + hw;
        #pragma unroll
        for (int d = 0; d < 64; ++d)
            obase[d * 4096] = srow[d] + bias[d];
    }
}

extern "C" void kernel_launch(void* const* d_in, const int* in_sizes, int n_in,
                              void* d_out, int out_size)
{
    const float* B    = (const float*)d_in[0];
    const float* W    = (const float*)d_in[1];
    const float* bias = (const float*)d_in[2];
    float* out = (float*)d_out;

    cvt_kernel<<<1024, 256>>>((const float4*)W);

    cudaFuncSetAttribute(fern_kernel, cudaFuncAttributeMaxDynamicSharedMemorySize, SMEM_BYTES);
    fern_kernel<<<NCTA, TPB, SMEM_BYTES>>>(B, bias, out);
}

// round 11
// speedup vs baseline: 1.0149x; 1.0149x over previous
#include <cuda_runtime.h>
#include <cuda_fp16.h>

// FernSparseTable v7b: half-table pipelined fills + predicated two-pass gathers,
// with v6 register-liveness profile (B prefetch after passes; slim phase-1).

#define TPB 512
#define NPX 131072
#define NCTA 296
#define PX_PER 443                   // ceil(131072/296); last CTA gets 387
#define TAB_BYTES 131072             // 1024 rows * 128 B
#define HALF_TAB 65536
#define PAR_STRIDE 80                // 8 probes * 8B + 16B pad
#define MBAR_OFF  (TAB_BYTES + TPB * PAR_STRIDE)   // 172032
#define SMEM_BYTES (MBAR_OFF + 16)                 // 172048

__device__ __align__(128) __half g_W16[16 * 1024 * 64];

__global__ void cvt_kernel(const float4* __restrict__ W)
{
    int i = blockIdx.x * blockDim.x + threadIdx.x;   // 262144 float4
    float4 v = W[i];
    __half2 a = __floats2half2_rn(v.x, v.y);
    __half2 b = __floats2half2_rn(v.z, v.w);
    uint2 r;
    r.x = *reinterpret_cast<unsigned*>(&a);
    r.y = *reinterpret_cast<unsigned*>(&b);
    reinterpret_cast<uint2*>(g_W16)[i] = r;
}

__device__ __forceinline__ __half2 u2h2(unsigned u) {
    return *reinterpret_cast<__half2*>(&u);
}

extern __shared__ char smem_raw[];

__device__ __forceinline__ void mbar_wait(unsigned mbar, unsigned parity)
{
    unsigned done;
    asm volatile(
        "{\n\t.reg .pred p;\n\t"
        "mbarrier.try_wait.parity.acquire.cta.shared::cta.b64 p, [%1], %2;\n\t"
        "selp.b32 %0, 1, 0, p;\n\t}"
        : "=r"(done) : "r"(mbar), "r"(parity) : "memory");
    if (!done) {
        asm volatile(
            "{\n\t.reg .pred P1;\n\t"
            "WL_%=:\n\t"
            "mbarrier.try_wait.parity.acquire.cta.shared::cta.b64 P1, [%0], %1, 0x989680;\n\t"
            "@P1 bra.uni WD_%=;\n\t"
            "bra.uni WL_%=;\n\t"
            "WD_%=:\n\t}"
            :: "r"(mbar), "r"(parity) : "memory");
    }
}

// Predicated probe: executes iff actdiff == 0 (row-half matches pass).
__device__ __forceinline__ void probe_pred(unsigned &h0, unsigned &h1,
                                           unsigned &h2, unsigned &h3,
                                           unsigned c, unsigned addr,
                                           unsigned actdiff)
{
    asm volatile(
        "{\n\t"
        ".reg .pred p;\n\t"
        ".reg .b32 w0, w1, w2, w3;\n\t"
        "setp.eq.u32 p, %6, 0;\n\t"
        "@p ld.shared.v4.b32 {w0, w1, w2, w3}, [%5];\n\t"
        "@p fma.rn.f16x2 %0, %4, w0, %0;\n\t"
        "@p fma.rn.f16x2 %1, %4, w1, %1;\n\t"
        "@p fma.rn.f16x2 %2, %4, w2, %2;\n\t"
        "@p fma.rn.f16x2 %3, %4, w3, %3;\n\t"
        "}"
        : "+r"(h0), "+r"(h1), "+r"(h2), "+r"(h3)
        : "r"(c), "r"(addr), "r"(actdiff));
}

__global__ __launch_bounds__(TPB, 1)
void fern_kernel(const float* __restrict__ B,
                 const float* __restrict__ bias,
                 float* __restrict__ out)
{
    char*  s_par = smem_raw + TAB_BYTES;
    float* s_out = (float*)smem_raw;         // epilogue reuse

    const int tid  = threadIdx.x;
    const int lane = tid & 31;
    const int warp = tid >> 5;

    const int base = blockIdx.x * PX_PER;
    const int cnt  = min(PX_PER, NPX - base);       // 443 or 387
    const int px   = min(base + tid, NPX - 1);      // clamped pixel id
    const bool valid = (base + tid) < NPX && tid < cnt;
    const int n  = px >> 12;
    const int hw = px & 4095;
    const int rem = cnt - warp * 32;                // per-warp tail bound

    unsigned smem_u32 = (unsigned)__cvta_generic_to_shared(smem_raw);
    const unsigned mb_lo = smem_u32 + MBAR_OFF;
    const unsigned mb_hi = mb_lo + 8;

    if (tid == 0) {
        asm volatile("mbarrier.init.shared.b64 [%0], 1;" :: "r"(mb_lo) : "memory");
        asm volatile("mbarrier.init.shared.b64 [%0], 1;" :: "r"(mb_hi) : "memory");
        asm volatile("fence.proxy.async.shared::cta;" ::: "memory");
    }

    const float* Bb = B + (n * 160) * 4096 + hw;
    const unsigned long long Wg =
        (unsigned long long)__cvta_generic_to_global(g_W16);

    float acc[64];
    #pragma unroll
    for (int i = 0; i < 64; ++i) acc[i] = 0.f;

    const unsigned gl_u32 = smem_u32 + (lane & 7) * 16;  // lane's 16B d-slice
    const int px_sub = lane >> 3;                        // 0..3

    auto issue_fill = [&](int m, int h) {
        const unsigned mb = h ? mb_hi : mb_lo;
        asm volatile("mbarrier.arrive.expect_tx.shared.b64 _, [%0], %1;"
                     :: "r"(mb), "r"(HALF_TAB) : "memory");
        unsigned long long src =
            Wg + (unsigned long long)m * 131072ull + (unsigned long long)h * HALF_TAB;
        unsigned dst = smem_u32 + h * HALF_TAB;
        #pragma unroll
        for (int c = 0; c < 2; ++c) {
            asm volatile(
                "cp.async.bulk.shared::cta.global.mbarrier::complete_tx::bytes "
                "[%0], [%1], %2, [%3];"
                :: "r"(dst + c * 32768), "l"(src + c * 32768ull),
                   "r"(32768), "r"(mb) : "memory");
        }
    };

    // slim phase-1: fern logic -> params, emitted incrementally (low live-set)
    auto phase1 = [&](const float* tv) {
        int wb = 0;
        float bsp = 1.f;
        #pragma unroll
        for (int k = 0; k < 10; ++k) {
            if (tv[k] >= 0.5f) wb |= (1 << k);
            bsp *= fmaxf(tv[k], 1.f - tv[k]);
        }
        int abi0, abi1, abi2;
        float av0, av1, av2;
        {
            float best = fabsf(tv[0] - 0.5f); int bi = 0; float bt = tv[0];
            #pragma unroll
            for (int k = 1; k < 10; ++k) {
                float ak = fabsf(tv[k] - 0.5f);
                if (ak < best) { best = ak; bi = k; bt = tv[k]; }
            }
            abi0 = bi; av0 = bt;
        }
        {
            float best = 3.0e38f; int bi = 0; float bt = 0.f;
            #pragma unroll
            for (int k = 0; k < 10; ++k) {
                float ak = fabsf(tv[k] - 0.5f);
                if (k != abi0 && ak < best) { best = ak; bi = k; bt = tv[k]; }
            }
            abi1 = bi; av1 = bt;
        }
        {
            float best = 3.0e38f; int bi = 0; float bt = 0.f;
            #pragma unroll
            for (int k = 0; k < 10; ++k) {
                float ak = fabsf(tv[k] - 0.5f);
                if (k != abi0 && k != abi1 && ak < best) { best = ak; bi = k; bt = tv[k]; }
            }
            abi2 = bi; av2 = bt;
        }

        const float d0 = 1.f - av0, d1 = 1.f - av1, d2 = 1.f - av2;
        const float denom = fmaxf(av0, d0) * fmaxf(av1, d1) * fmaxf(av2, d2);
        const float bspp = valid ? (bsp / denom) : 0.f;
        const float g0 = bspp * d0, g1 = bspp * av0;

        const int m0 = 1 << abi0, m1 = 1 << abi1, m2 = 1 << abi2;
        const int b0 = wb & ~(m0 | m1 | m2);

        uint4* myp = (uint4*)(s_par + tid * PAR_STRIDE);
        #pragma unroll
        for (int jj = 0; jj < 4; ++jj) {
            const float s1 = (jj & 1) ? av1 : d1;
            const float s2 = (jj & 2) ? av2 : d2;
            const float s12 = s1 * s2;
            __half2 he = __floats2half2_rn(g0 * s12, g0 * s12);
            __half2 ho = __floats2half2_rn(g1 * s12, g1 * s12);
            int oe = (b0 | ((jj & 1) ? m1 : 0) | ((jj & 2) ? m2 : 0)) << 7;
            int oo = oe | (m0 << 7);
            myp[jj] = make_uint4(*reinterpret_cast<unsigned*>(&he), (unsigned)oe,
                                 *reinterpret_cast<unsigned*>(&ho), (unsigned)oo);
        }
        __syncwarp();
    };

    // one predicated gather pass over this warp's pixel groups
    auto gather_pass = [&](unsigned pass) {
        #pragma unroll
        for (int g = 0; g < 8; ++g) {
            if (g * 4 < rem) {
                const uint4* pp =
                    (const uint4*)(s_par + (warp * 32 + g * 4 + px_sub) * PAR_STRIDE);
                unsigned h0 = 0, h1 = 0, h2 = 0, h3 = 0;
                #pragma unroll
                for (int jj = 0; jj < 4; ++jj) {
                    uint4 pr = pp[jj];
                    probe_pred(h0, h1, h2, h3, pr.x, gl_u32 + pr.y,
                               (pr.y >> 16) ^ pass);
                    probe_pred(h0, h1, h2, h3, pr.z, gl_u32 + pr.w,
                               (pr.w >> 16) ^ pass);
                }
                float2 f0 = __half22float2(u2h2(h0));
                float2 f1 = __half22float2(u2h2(h1));
                float2 f2 = __half22float2(u2h2(h2));
                float2 f3 = __half22float2(u2h2(h3));
                acc[g*8+0] += f0.x; acc[g*8+1] += f0.y;
                acc[g*8+2] += f1.x; acc[g*8+3] += f1.y;
                acc[g*8+4] += f2.x; acc[g*8+5] += f2.y;
                acc[g*8+6] += f3.x; acc[g*8+7] += f3.y;
            }
        }
    };

    // ---- prologue ----
    float tn[10];
    {
        float tc[10];
        #pragma unroll
        for (int k = 0; k < 10; ++k) tc[k] = Bb[k * 4096];
        #pragma unroll
        for (int k = 0; k < 10; ++k) tn[k] = Bb[40960 + k * 4096];
        phase1(tc);
    }
    __syncthreads();            // mbar init visible before any wait
    if (tid == 0) { issue_fill(0, 0); issue_fill(0, 1); }

    #pragma unroll 1
    for (int m = 0; m < 16; ++m) {
        const unsigned parity = (unsigned)(m & 1);

        // ---- pass 0: rows [0,512) ----
        mbar_wait(mb_lo, parity);
        gather_pass(0u);
        if (m < 15) {
            if (warp == 0) {
                asm volatile("bar.sync 1, 512;" ::: "memory");
                if (tid == 0) issue_fill(m + 1, 0);
            } else {
                asm volatile("bar.arrive 1, 512;" ::: "memory");
            }
        }

        // ---- pass 1: rows [512,1024) ----
        mbar_wait(mb_hi, parity);
        gather_pass(1u);
        if (m < 15) {
            if (warp == 0) {
                asm volatile("bar.sync 2, 512;" ::: "memory");
                if (tid == 0) issue_fill(m + 1, 1);
            } else {
                asm volatile("bar.arrive 2, 512;" ::: "memory");
            }

            // prefetch B for fern m+2 (live only across phase1, as in v6)
            float t2[10];
            {
                const int mn = (m + 2 < 16) ? (m + 2) : 15;
                const float* pf = Bb + mn * 40960;
                #pragma unroll
                for (int k = 0; k < 10; ++k) t2[k] = pf[k * 4096];
            }
            phase1(tn);
            #pragma unroll
            for (int k = 0; k < 10; ++k) tn[k] = t2[k];
        }
    }

    // ---- epilogue: stride-65 transpose -> coalesced stores ----
    __syncthreads();
    #pragma unroll
    for (int g = 0; g < 8; ++g) {
        int pxl = warp * 32 + g * 4 + px_sub;
        float* row = s_out + pxl * 65 + (lane & 7) * 8;
        #pragma unroll
        for (int r = 0; r < 8; ++r) row[r] = acc[g * 8 + r];
    }
    __syncthreads();

    if (valid) {
        const float* srow = s_out + tid * 65;
        float* obase = out + (n * 64) * 4096 + hw;
        #pragma unroll
        for (int d = 0; d < 64; ++d)
            obase[d * 4096] = srow[d] + bias[d];
    }
}

extern "C" void kernel_launch(void* const* d_in, const int* in_sizes, int n_in,
                              void* d_out, int out_size)
{
    const float* B    = (const float*)d_in[0];
    const float* W    = (const float*)d_in[1];
    const float* bias = (const float*)d_in[2];
    float* out = (float*)d_out;

    cvt_kernel<<<1024, 256>>>((const float4*)W);

    cudaFuncSetAttribute(fern_kernel, cudaFuncAttributeMaxDynamicSharedMemorySize, SMEM_BYTES);
    fern_kernel<<<NCTA, TPB, SMEM_BYTES>>>(B, bias, out);
}

// round 12
// speedup vs baseline: 13.3358x; 13.1401x over previous
#include <cuda_runtime.h>
#include <cuda_fp16.h>

// FernSparseTable v8: v6 (proven 133us) + per-CTA fern staggering.
//  CTA i processes ferns in order (s + i) mod 16, desynchronizing the chip-wide
//  fill bursts at fern boundaries: L2 fill demand averages 2.5KB/cyc instead of
//  19MB bursts at the 6.3KB/cyc LTS cap -> fill latency ~3K -> ~1.2K cyc.

#define TPB 512
#define NPX 131072
#define NCTA 296
#define PX_PER 443                   // ceil(131072/296); last CTA gets 387
#define TAB_BYTES 131072             // 1024 rows * 128 B
#define PAR_STRIDE 80                // 8 probes * 8B + 16B pad
#define MBAR_OFF  (TAB_BYTES + TPB * PAR_STRIDE)   // 172032
#define SMEM_BYTES (MBAR_OFF + 16)                 // 172048

__device__ __align__(128) __half g_W16[16 * 1024 * 64];

__global__ void cvt_kernel(const float4* __restrict__ W)
{
    int i = blockIdx.x * blockDim.x + threadIdx.x;   // 262144 float4
    float4 v = W[i];
    __half2 a = __floats2half2_rn(v.x, v.y);
    __half2 b = __floats2half2_rn(v.z, v.w);
    uint2 r;
    r.x = *reinterpret_cast<unsigned*>(&a);
    r.y = *reinterpret_cast<unsigned*>(&b);
    reinterpret_cast<uint2*>(g_W16)[i] = r;
}

__device__ __forceinline__ __half2 u2h2(unsigned u) {
    return *reinterpret_cast<__half2*>(&u);
}

extern __shared__ char smem_raw[];

__device__ __forceinline__ void mbar_wait(unsigned mbar, unsigned parity)
{
    unsigned done;
    asm volatile(
        "{\n\t.reg .pred p;\n\t"
        "mbarrier.try_wait.parity.acquire.cta.shared::cta.b64 p, [%1], %2;\n\t"
        "selp.b32 %0, 1, 0, p;\n\t}"
        : "=r"(done) : "r"(mbar), "r"(parity) : "memory");
    if (!done) {
        asm volatile(
            "{\n\t.reg .pred P1;\n\t"
            "WL_%=:\n\t"
            "mbarrier.try_wait.parity.acquire.cta.shared::cta.b64 P1, [%0], %1, 0x989680;\n\t"
            "@P1 bra.uni WD_%=;\n\t"
            "bra.uni WL_%=;\n\t"
            "WD_%=:\n\t}"
            :: "r"(mbar), "r"(parity) : "memory");
    }
}

__global__ __launch_bounds__(TPB, 1)
void fern_kernel(const float* __restrict__ B,
                 const float* __restrict__ bias,
                 float* __restrict__ out)
{
    char*  s_tab = smem_raw;
    char*  s_par = smem_raw + TAB_BYTES;
    float* s_out = (float*)smem_raw;         // epilogue reuse

    const int tid  = threadIdx.x;
    const int lane = tid & 31;
    const int warp = tid >> 5;

    const int base = blockIdx.x * PX_PER;
    const int cnt  = min(PX_PER, NPX - base);       // 443 or 387
    const int px   = min(base + tid, NPX - 1);      // clamped pixel id
    const bool valid = (base + tid) < NPX && tid < cnt;
    const int n  = px >> 12;
    const int hw = px & 4095;
    const int rem = cnt - warp * 32;                // per-warp tail bound
    const int moff = blockIdx.x & 15;               // fern stagger offset

    unsigned smem_u32 = (unsigned)__cvta_generic_to_shared(smem_raw);
    const unsigned mbar = smem_u32 + MBAR_OFF;

    if (tid == 0) {
        asm volatile("mbarrier.init.shared.b64 [%0], 1;" :: "r"(mbar) : "memory");
        asm volatile("fence.proxy.async.shared::cta;" ::: "memory");
    }

    const float* Bb = B + (n * 160) * 4096 + hw;
    const unsigned long long Wg =
        (unsigned long long)__cvta_generic_to_global(g_W16);

    float acc[64];
    #pragma unroll
    for (int i = 0; i < 64; ++i) acc[i] = 0.f;

    const char* gl = s_tab + (lane & 7) * 16;    // lane's 16B d-slice in a 128B row
    const int px_sub = lane >> 3;                // 0..3

    // fill-issue helper (tid 0 only); f = actual fern index
    auto issue_fill = [&](int f) {
        asm volatile("mbarrier.arrive.expect_tx.shared.b64 _, [%0], %1;"
                     :: "r"(mbar), "r"(TAB_BYTES) : "memory");
        unsigned long long src = Wg + (unsigned long long)f * 131072ull;
        #pragma unroll
        for (int c = 0; c < 4; ++c) {
            asm volatile(
                "cp.async.bulk.shared::cta.global.mbarrier::complete_tx::bytes "
                "[%0], [%1], %2, [%3];"
                :: "r"(smem_u32 + c * 32768), "l"(src + c * 32768ull),
                   "r"(32768), "r"(mbar) : "memory");
        }
    };

    // phase-1: fern logic on register array tv -> params in smem (warp-local)
    auto phase1 = [&](const float* tv) {
        int wb = 0;
        float bsp = 1.f;
        #pragma unroll
        for (int k = 0; k < 10; ++k) {
            if (tv[k] >= 0.5f) wb |= (1 << k);
            bsp *= fmaxf(tv[k], 1.f - tv[k]);
        }
        int abi0, abi1, abi2;
        float av0, av1, av2;
        {
            float best = fabsf(tv[0] - 0.5f); int bi = 0; float bt = tv[0];
            #pragma unroll
            for (int k = 1; k < 10; ++k) {
                float ak = fabsf(tv[k] - 0.5f);
                if (ak < best) { best = ak; bi = k; bt = tv[k]; }
            }
            abi0 = bi; av0 = bt;
        }
        {
            float best = 3.0e38f; int bi = 0; float bt = 0.f;
            #pragma unroll
            for (int k = 0; k < 10; ++k) {
                float ak = fabsf(tv[k] - 0.5f);
                if (k != abi0 && ak < best) { best = ak; bi = k; bt = tv[k]; }
            }
            abi1 = bi; av1 = bt;
        }
        {
            float best = 3.0e38f; int bi = 0; float bt = 0.f;
            #pragma unroll
            for (int k = 0; k < 10; ++k) {
                float ak = fabsf(tv[k] - 0.5f);
                if (k != abi0 && k != abi1 && ak < best) { best = ak; bi = k; bt = tv[k]; }
            }
            abi2 = bi; av2 = bt;
        }

        const float d0 = 1.f - av0, d1 = 1.f - av1, d2 = 1.f - av2;
        const float denom = fmaxf(av0, d0) * fmaxf(av1, d1) * fmaxf(av2, d2);
        const float bspp = valid ? (bsp / denom) : 0.f;

        float cp[8];
        {
            float g0 = bspp * d0,  g1 = bspp * av0;
            float c00 = g0 * d1,  c10 = g1 * d1;
            float c01 = g0 * av1, c11 = g1 * av1;
            cp[0] = c00 * d2;  cp[1] = c10 * d2;  cp[2] = c01 * d2;  cp[3] = c11 * d2;
            cp[4] = c00 * av2; cp[5] = c10 * av2; cp[6] = c01 * av2; cp[7] = c11 * av2;
        }
        unsigned ch[8];
        #pragma unroll
        for (int j = 0; j < 8; ++j) {
            __half2 hh = __floats2half2_rn(cp[j], cp[j]);
            ch[j] = *reinterpret_cast<unsigned*>(&hh);
        }
        int io[8];
        {
            const int m0 = 1 << abi0, m1 = 1 << abi1, m2 = 1 << abi2;
            const int b0 = wb & ~(m0 | m1 | m2);
            const int i0 = b0, i1 = b0 | m0, i2 = b0 | m1, i3 = b0 | m0 | m1;
            io[0] = i0 << 7;        io[1] = i1 << 7;
            io[2] = i2 << 7;        io[3] = i3 << 7;
            io[4] = (i0 | m2) << 7; io[5] = (i1 | m2) << 7;
            io[6] = (i2 | m2) << 7; io[7] = (i3 | m2) << 7;
        }
        uint4* myp = (uint4*)(s_par + tid * PAR_STRIDE);
        #pragma unroll
        for (int jj = 0; jj < 4; ++jj)
            myp[jj] = make_uint4(ch[2*jj], (unsigned)io[2*jj],
                                 ch[2*jj+1], (unsigned)io[2*jj+1]);
        __syncwarp();
    };

    // ---- prologue: B for staggered ferns f(0), f(1); phase1(f(0)); fill f(0) ----
    float tc[10], tn[10];
    {
        const float* p0 = Bb + moff * 40960;
        #pragma unroll
        for (int k = 0; k < 10; ++k) tc[k] = p0[k * 4096];
        const float* p1 = Bb + ((moff + 1) & 15) * 40960;
        #pragma unroll
        for (int k = 0; k < 10; ++k) tn[k] = p1[k * 4096];
    }
    phase1(tc);
    __syncthreads();            // mbar init visible before any wait
    if (tid == 0) issue_fill(moff);

    #pragma unroll 1
    for (int m = 0; m < 16; ++m) {
        mbar_wait(mbar, (unsigned)(m & 1));

        // ---- phase 2: HFMA2 gathers, 4 px per instruction; tail groups skipped ----
        #pragma unroll
        for (int g = 0; g < 8; ++g) {
            if (g * 4 < rem) {                    // warp-uniform guard
                const uint4* pp =
                    (const uint4*)(s_par + (warp * 32 + g * 4 + px_sub) * PAR_STRIDE);
                __half2 h0 = __floats2half2_rn(0.f, 0.f);
                __half2 h1 = h0, h2 = h0, h3 = h0;
                #pragma unroll
                for (int jj = 0; jj < 4; ++jj) {
                    uint4 pr = pp[jj];
                    {
                        __half2 c = u2h2(pr.x);
                        uint4 w4 = *(const uint4*)(gl + pr.y);
                        h0 = __hfma2(c, u2h2(w4.x), h0);
                        h1 = __hfma2(c, u2h2(w4.y), h1);
                        h2 = __hfma2(c, u2h2(w4.z), h2);
                        h3 = __hfma2(c, u2h2(w4.w), h3);
                    }
                    {
                        __half2 c = u2h2(pr.z);
                        uint4 w4 = *(const uint4*)(gl + pr.w);
                        h0 = __hfma2(c, u2h2(w4.x), h0);
                        h1 = __hfma2(c, u2h2(w4.y), h1);
                        h2 = __hfma2(c, u2h2(w4.z), h2);
                        h3 = __hfma2(c, u2h2(w4.w), h3);
                    }
                }
                float2 f0 = __half22float2(h0);
                float2 f1 = __half22float2(h1);
                float2 f2 = __half22float2(h2);
                float2 f3 = __half22float2(h3);
                acc[g*8+0] += f0.x; acc[g*8+1] += f0.y;
                acc[g*8+2] += f1.x; acc[g*8+3] += f1.y;
                acc[g*8+4] += f2.x; acc[g*8+5] += f2.y;
                acc[g*8+6] += f3.x; acc[g*8+7] += f3.y;
            }
        }

        if (m < 15) {
            // table-free gate: warps 1-15 arrive and proceed; warp 0 waits for all,
            // then issues the next fill. Early warps overlap phase-1 with late gathers.
            if (warp == 0) {
                asm volatile("bar.sync 1, 512;" ::: "memory");
                if (tid == 0) issue_fill((m + 1 + moff) & 15);
            } else {
                asm volatile("bar.arrive 1, 512;" ::: "memory");
            }

            // prefetch B for staggered fern f(m+2) (wraps; always a valid fern)
            float t2[10];
            {
                const float* pf = Bb + ((m + 2 + moff) & 15) * 40960;
                #pragma unroll
                for (int k = 0; k < 10; ++k) t2[k] = pf[k * 4096];
            }

            phase1(tn);           // params for fern f(m+1)

            #pragma unroll
            for (int k = 0; k < 10; ++k) tn[k] = t2[k];
        }
    }

    // ---- epilogue: stride-65 transpose -> coalesced stores ----
    __syncthreads();
    #pragma unroll
    for (int g = 0; g < 8; ++g) {
        int pxl = warp * 32 + g * 4 + px_sub;
        float* row = s_out + pxl * 65 + (lane & 7) * 8;
        #pragma unroll
        for (int r = 0; r < 8; ++r) row[r] = acc[g * 8 + r];
    }
    __syncthreads();

    if (valid) {
        const float* srow = s_out + tid * 65;
        float* obase = out + (n * 64) * 4096 + hw;
        #pragma unroll
        for (int d = 0; d < 64; ++d)
            obase[d * 4096] = srow[d] + bias[d];
    }
}

extern "C" void kernel_launch(void* const* d_in, const int* in_sizes, int n_in,
                              void* d_out, int out_size)
{
    const float* B    = (const float*)d_in[0];
    const float* W    = (const float*)d_in[1];
    const float* bias = (const float*)d_in[2];
    float* out = (float*)d_out;

    cvt_kernel<<<1024, 256>>>((const float4*)W);

    cudaFuncSetAttribute(fern_kernel, cudaFuncAttributeMaxDynamicSharedMemorySize, SMEM_BYTES);
    fern_kernel<<<NCTA, TPB, SMEM_BYTES>>>(B, bias, out);
}

// round 13
// speedup vs baseline: 13.7426x; 1.0305x over previous
#include <cuda_runtime.h>
#include <cuda_fp16.h>

// FernSparseTable v9: v6 core + partial double-buffered table fills.
//  hi rows [448,1024) (72KB) single-buffered (exposed fill, gated per fern);
//  lo rows [0,448)   (56KB) double-buffered (fill overlaps the next fern's gathers).
//  Gather address: branch-free select between lo buffer (by fern parity) and hi region.

#define TPB 512
#define NPX 131072
#define NCTA 296
#define PX_PER 443                   // ceil(131072/296); last CTA gets 387
#define LOSZ 57344                   // 448 rows * 128B
#define HISZ 73728                   // 576 rows * 128B
#define OFF_HI 0
#define OFF_L0 73728
#define OFF_L1 131072
#define PAR_OFF 188416
#define PAR_STRIDE 80                // 8 probes * 8B + 16B pad
#define MBAR_OFF 229376              // PAR_OFF + 512*80
#define SMEM_BYTES 229408            // + 3 mbarriers (24B) + pad

__device__ __align__(128) __half g_W16[16 * 1024 * 64];

__global__ void cvt_kernel(const float4* __restrict__ W)
{
    int i = blockIdx.x * blockDim.x + threadIdx.x;   // 262144 float4
    float4 v = W[i];
    __half2 a = __floats2half2_rn(v.x, v.y);
    __half2 b = __floats2half2_rn(v.z, v.w);
    uint2 r;
    r.x = *reinterpret_cast<unsigned*>(&a);
    r.y = *reinterpret_cast<unsigned*>(&b);
    reinterpret_cast<uint2*>(g_W16)[i] = r;
}

__device__ __forceinline__ __half2 u2h2(unsigned u) {
    return *reinterpret_cast<__half2*>(&u);
}

extern __shared__ char smem_raw[];

__device__ __forceinline__ void mbar_wait(unsigned mbar, unsigned parity)
{
    unsigned done;
    asm volatile(
        "{\n\t.reg .pred p;\n\t"
        "mbarrier.try_wait.parity.acquire.cta.shared::cta.b64 p, [%1], %2;\n\t"
        "selp.b32 %0, 1, 0, p;\n\t}"
        : "=r"(done) : "r"(mbar), "r"(parity) : "memory");
    if (!done) {
        asm volatile(
            "{\n\t.reg .pred P1;\n\t"
            "WL_%=:\n\t"
            "mbarrier.try_wait.parity.acquire.cta.shared::cta.b64 P1, [%0], %1, 0x989680;\n\t"
            "@P1 bra.uni WD_%=;\n\t"
            "bra.uni WL_%=;\n\t"
            "WD_%=:\n\t}"
            :: "r"(mbar), "r"(parity) : "memory");
    }
}

__global__ __launch_bounds__(TPB, 1)
void fern_kernel(const float* __restrict__ B,
                 const float* __restrict__ bias,
                 float* __restrict__ out)
{
    char*  s_par = smem_raw + PAR_OFF;
    float* s_out = (float*)smem_raw;         // epilogue reuse

    const int tid  = threadIdx.x;
    const int lane = tid & 31;
    const int warp = tid >> 5;

    const int base = blockIdx.x * PX_PER;
    const int cnt  = min(PX_PER, NPX - base);       // 443 or 387
    const int px   = min(base + tid, NPX - 1);      // clamped pixel id
    const bool valid = (base + tid) < NPX && tid < cnt;
    const int n  = px >> 12;
    const int hw = px & 4095;
    const int rem = cnt - warp * 32;                // per-warp tail bound

    unsigned smem_u32 = (unsigned)__cvta_generic_to_shared(smem_raw);
    const unsigned mb_hi = smem_u32 + MBAR_OFF;
    const unsigned mb_l0 = mb_hi + 8;
    const unsigned mb_l1 = mb_hi + 16;

    if (tid == 0) {
        asm volatile("mbarrier.init.shared.b64 [%0], 1;" :: "r"(mb_hi) : "memory");
        asm volatile("mbarrier.init.shared.b64 [%0], 1;" :: "r"(mb_l0) : "memory");
        asm volatile("mbarrier.init.shared.b64 [%0], 1;" :: "r"(mb_l1) : "memory");
        asm volatile("fence.proxy.async.shared::cta;" ::: "memory");
    }

    const float* Bb = B + (n * 160) * 4096 + hw;
    const unsigned long long Wg =
        (unsigned long long)__cvta_generic_to_global(g_W16);

    float acc[64];
    #pragma unroll
    for (int i = 0; i < 64; ++i) acc[i] = 0.f;

    const char* glp = smem_raw + (lane & 7) * 16;   // lane's 16B d-slice base
    const int px_sub = lane >> 3;                    // 0..3

    // hi-fill: rows [448,1024) of fern f -> OFF_HI (72KB)
    auto issue_fill_hi = [&](int f) {
        asm volatile("mbarrier.arrive.expect_tx.shared.b64 _, [%0], %1;"
                     :: "r"(mb_hi), "r"(HISZ) : "memory");
        unsigned long long src = Wg + (unsigned long long)f * 131072ull + LOSZ;
        #pragma unroll
        for (int c = 0; c < 2; ++c) {
            asm volatile(
                "cp.async.bulk.shared::cta.global.mbarrier::complete_tx::bytes "
                "[%0], [%1], %2, [%3];"
                :: "r"(smem_u32 + OFF_HI + c * 36864), "l"(src + c * 36864ull),
                   "r"(36864), "r"(mb_hi) : "memory");
        }
    };
    // lo-fill: rows [0,448) of fern f -> lo buffer b (56KB)
    auto issue_fill_lo = [&](int f, int b) {
        const unsigned mb = b ? mb_l1 : mb_l0;
        const unsigned dst = smem_u32 + (b ? OFF_L1 : OFF_L0);
        asm volatile("mbarrier.arrive.expect_tx.shared.b64 _, [%0], %1;"
                     :: "r"(mb), "r"(LOSZ) : "memory");
        unsigned long long src = Wg + (unsigned long long)f * 131072ull;
        #pragma unroll
        for (int c = 0; c < 2; ++c) {
            asm volatile(
                "cp.async.bulk.shared::cta.global.mbarrier::complete_tx::bytes "
                "[%0], [%1], %2, [%3];"
                :: "r"(dst + c * 28672), "l"(src + c * 28672ull),
                   "r"(28672), "r"(mb) : "memory");
        }
    };

    // phase-1: fern logic on register array tv -> params in smem (warp-local)
    auto phase1 = [&](const float* tv) {
        int wb = 0;
        float bsp = 1.f;
        #pragma unroll
        for (int k = 0; k < 10; ++k) {
            if (tv[k] >= 0.5f) wb |= (1 << k);
            bsp *= fmaxf(tv[k], 1.f - tv[k]);
        }
        int abi0, abi1, abi2;
        float av0, av1, av2;
        {
            float best = fabsf(tv[0] - 0.5f); int bi = 0; float bt = tv[0];
            #pragma unroll
            for (int k = 1; k < 10; ++k) {
                float ak = fabsf(tv[k] - 0.5f);
                if (ak < best) { best = ak; bi = k; bt = tv[k]; }
            }
            abi0 = bi; av0 = bt;
        }
        {
            float best = 3.0e38f; int bi = 0; float bt = 0.f;
            #pragma unroll
            for (int k = 0; k < 10; ++k) {
                float ak = fabsf(tv[k] - 0.5f);
                if (k != abi0 && ak < best) { best = ak; bi = k; bt = tv[k]; }
            }
            abi1 = bi; av1 = bt;
        }
        {
            float best = 3.0e38f; int bi = 0; float bt = 0.f;
            #pragma unroll
            for (int k = 0; k < 10; ++k) {
                float ak = fabsf(tv[k] - 0.5f);
                if (k != abi0 && k != abi1 && ak < best) { best = ak; bi = k; bt = tv[k]; }
            }
            abi2 = bi; av2 = bt;
        }

        const float d0 = 1.f - av0, d1 = 1.f - av1, d2 = 1.f - av2;
        const float denom = fmaxf(av0, d0) * fmaxf(av1, d1) * fmaxf(av2, d2);
        const float bspp = valid ? (bsp / denom) : 0.f;

        float cp[8];
        {
            float g0 = bspp * d0,  g1 = bspp * av0;
            float c00 = g0 * d1,  c10 = g1 * d1;
            float c01 = g0 * av1, c11 = g1 * av1;
            cp[0] = c00 * d2;  cp[1] = c10 * d2;  cp[2] = c01 * d2;  cp[3] = c11 * d2;
            cp[4] = c00 * av2; cp[5] = c10 * av2; cp[6] = c01 * av2; cp[7] = c11 * av2;
        }
        unsigned ch[8];
        #pragma unroll
        for (int j = 0; j < 8; ++j) {
            __half2 hh = __floats2half2_rn(cp[j], cp[j]);
            ch[j] = *reinterpret_cast<unsigned*>(&hh);
        }
        int io[8];
        {
            const int m0 = 1 << abi0, m1 = 1 << abi1, m2 = 1 << abi2;
            const int b0 = wb & ~(m0 | m1 | m2);
            const int i0 = b0, i1 = b0 | m0, i2 = b0 | m1, i3 = b0 | m0 | m1;
            io[0] = i0 << 7;        io[1] = i1 << 7;
            io[2] = i2 << 7;        io[3] = i3 << 7;
            io[4] = (i0 | m2) << 7; io[5] = (i1 | m2) << 7;
            io[6] = (i2 | m2) << 7; io[7] = (i3 | m2) << 7;
        }
        uint4* myp = (uint4*)(s_par + tid * PAR_STRIDE);
        #pragma unroll
        for (int jj = 0; jj < 4; ++jj)
            myp[jj] = make_uint4(ch[2*jj], (unsigned)io[2*jj],
                                 ch[2*jj+1], (unsigned)io[2*jj+1]);
        __syncwarp();
    };

    // ---- prologue: B for ferns 0,1; phase1(0); prime fills ----
    float tc[10], tn[10];
    #pragma unroll
    for (int k = 0; k < 10; ++k) tc[k] = Bb[k * 4096];
    #pragma unroll
    for (int k = 0; k < 10; ++k) tn[k] = Bb[40960 + k * 4096];
    phase1(tc);
    __syncthreads();            // mbar init visible before any wait
    if (tid == 0) {
        issue_fill_lo(0, 0);
        issue_fill_hi(0);
        issue_fill_lo(1, 1);
    }

    #pragma unroll 1
    for (int m = 0; m < 16; ++m) {
        mbar_wait(mb_hi, (unsigned)(m & 1));
        mbar_wait((m & 1) ? mb_l1 : mb_l0, (unsigned)((m >> 1) & 1));

        const int lo_add = (m & 1) ? OFF_L1 : OFF_L0;

        // ---- phase 2: HFMA2 gathers with lo/hi base select ----
        #pragma unroll
        for (int g = 0; g < 8; ++g) {
            if (g * 4 < rem) {                    // warp-uniform guard
                const uint4* pp =
                    (const uint4*)(s_par + (warp * 32 + g * 4 + px_sub) * PAR_STRIDE);
                __half2 h0 = __floats2half2_rn(0.f, 0.f);
                __half2 h1 = h0, h2 = h0, h3 = h0;
                #pragma unroll
                for (int jj = 0; jj < 4; ++jj) {
                    uint4 pr = pp[jj];
                    {
                        int oy = (int)pr.y;
                        const char* p0 = glp + (oy < LOSZ ? oy + lo_add : oy - LOSZ);
                        __half2 c = u2h2(pr.x);
                        uint4 w4 = *(const uint4*)p0;
                        h0 = __hfma2(c, u2h2(w4.x), h0);
                        h1 = __hfma2(c, u2h2(w4.y), h1);
                        h2 = __hfma2(c, u2h2(w4.z), h2);
                        h3 = __hfma2(c, u2h2(w4.w), h3);
                    }
                    {
                        int ow = (int)pr.w;
                        const char* p1 = glp + (ow < LOSZ ? ow + lo_add : ow - LOSZ);
                        __half2 c = u2h2(pr.z);
                        uint4 w4 = *(const uint4*)p1;
                        h0 = __hfma2(c, u2h2(w4.x), h0);
                        h1 = __hfma2(c, u2h2(w4.y), h1);
                        h2 = __hfma2(c, u2h2(w4.z), h2);
                        h3 = __hfma2(c, u2h2(w4.w), h3);
                    }
                }
                float2 f0 = __half22float2(h0);
                float2 f1 = __half22float2(h1);
                float2 f2 = __half22float2(h2);
                float2 f3 = __half22float2(h3);
                acc[g*8+0] += f0.x; acc[g*8+1] += f0.y;
                acc[g*8+2] += f1.x; acc[g*8+3] += f1.y;
                acc[g*8+4] += f2.x; acc[g*8+5] += f2.y;
                acc[g*8+6] += f3.x; acc[g*8+7] += f3.y;
            }
        }

        if (m < 15) {
            // gate: all warps done with fern m's table regions
            if (warp == 0) {
                asm volatile("bar.sync 1, 512;" ::: "memory");
                if (tid == 0) {
                    issue_fill_hi(m + 1);                       // exposed next iter
                    if (m < 14) issue_fill_lo(m + 2, m & 1);    // overlaps next iter
                }
            } else {
                asm volatile("bar.arrive 1, 512;" ::: "memory");
            }

            // prefetch B for fern m+2
            float t2[10];
            {
                const int mn = (m + 2 < 16) ? (m + 2) : 15;
                const float* pf = Bb + mn * 40960;
                #pragma unroll
                for (int k = 0; k < 10; ++k) t2[k] = pf[k * 4096];
            }

            phase1(tn);           // fern m+1 params

            #pragma unroll
            for (int k = 0; k < 10; ++k) tn[k] = t2[k];
        }
    }

    // ---- epilogue: stride-65 transpose -> coalesced stores ----
    __syncthreads();
    #pragma unroll
    for (int g = 0; g < 8; ++g) {
        int pxl = warp * 32 + g * 4 + px_sub;
        float* row = s_out + pxl * 65 + (lane & 7) * 8;
        #pragma unroll
        for (int r = 0; r < 8; ++r) row[r] = acc[g * 8 + r];
    }
    __syncthreads();

    if (valid) {
        const float* srow = s_out + tid * 65;
        float* obase = out + (n * 64) * 4096 + hw;
        #pragma unroll
        for (int d = 0; d < 64; ++d)
            obase[d * 4096] = srow[d] + bias[d];
    }
}

extern "C" void kernel_launch(void* const* d_in, const int* in_sizes, int n_in,
                              void* d_out, int out_size)
{
    const float* B    = (const float*)d_in[0];
    const float* W    = (const float*)d_in[1];
    const float* bias = (const float*)d_in[2];
    float* out = (float*)d_out;

    cvt_kernel<<<1024, 256>>>((const float4*)W);

    cudaFuncSetAttribute(fern_kernel, cudaFuncAttributeMaxDynamicSharedMemorySize, SMEM_BYTES);
    fern_kernel<<<NCTA, TPB, SMEM_BYTES>>>(B, bias, out);
}

// round 15
// speedup vs baseline: 13.7558x; 1.0010x over previous
#include <cuda_runtime.h>
#include <cuda_fp16.h>

// FernSparseTable v10: v9 (partial double-buffered fills) with the lo/hi address
//  select moved into phase-1 (8 selects/thread/fern instead of 64 in phase-2).
//  Phase-2 gather body is byte-identical to the proven v6 code.

#define TPB 512
#define NPX 131072
#define NCTA 296
#define PX_PER 443                   // ceil(131072/296); last CTA gets 387
#define LOSZ 57344                   // 448 rows * 128B
#define HISZ 73728                   // 576 rows * 128B
#define OFF_HI 0
#define OFF_L0 73728
#define OFF_L1 131072
#define PAR_OFF 188416
#define PAR_STRIDE 80                // 8 probes * 8B + 16B pad
#define MBAR_OFF 229376              // PAR_OFF + 512*80
#define SMEM_BYTES 229408            // + 3 mbarriers (24B) + pad

__device__ __align__(128) __half g_W16[16 * 1024 * 64];

__global__ void cvt_kernel(const float4* __restrict__ W)
{
    int i = blockIdx.x * blockDim.x + threadIdx.x;   // 262144 float4
    float4 v = W[i];
    __half2 a = __floats2half2_rn(v.x, v.y);
    __half2 b = __floats2half2_rn(v.z, v.w);
    uint2 r;
    r.x = *reinterpret_cast<unsigned*>(&a);
    r.y = *reinterpret_cast<unsigned*>(&b);
    reinterpret_cast<uint2*>(g_W16)[i] = r;
}

__device__ __forceinline__ __half2 u2h2(unsigned u) {
    return *reinterpret_cast<__half2*>(&u);
}

extern __shared__ char smem_raw[];

__device__ __forceinline__ void mbar_wait(unsigned mbar, unsigned parity)
{
    unsigned done;
    asm volatile(
        "{\n\t.reg .pred p;\n\t"
        "mbarrier.try_wait.parity.acquire.cta.shared::cta.b64 p, [%1], %2;\n\t"
        "selp.b32 %0, 1, 0, p;\n\t}"
        : "=r"(done) : "r"(mbar), "r"(parity) : "memory");
    if (!done) {
        asm volatile(
            "{\n\t.reg .pred P1;\n\t"
            "WL_%=:\n\t"
            "mbarrier.try_wait.parity.acquire.cta.shared::cta.b64 P1, [%0], %1, 0x989680;\n\t"
            "@P1 bra.uni WD_%=;\n\t"
            "bra.uni WL_%=;\n\t"
            "WD_%=:\n\t}"
            :: "r"(mbar), "r"(parity) : "memory");
    }
}

__global__ __launch_bounds__(TPB, 1)
void fern_kernel(const float* __restrict__ B,
                 const float* __restrict__ bias,
                 float* __restrict__ out)
{
    char*  s_par = smem_raw + PAR_OFF;
    float* s_out = (float*)smem_raw;         // epilogue reuse

    const int tid  = threadIdx.x;
    const int lane = tid & 31;
    const int warp = tid >> 5;

    const int base = blockIdx.x * PX_PER;
    const int cnt  = min(PX_PER, NPX - base);       // 443 or 387
    const int px   = min(base + tid, NPX - 1);      // clamped pixel id
    const bool valid = (base + tid) < NPX && tid < cnt;
    const int n  = px >> 12;
    const int hw = px & 4095;
    const int rem = cnt - warp * 32;                // per-warp tail bound

    unsigned smem_u32 = (unsigned)__cvta_generic_to_shared(smem_raw);
    const unsigned mb_hi = smem_u32 + MBAR_OFF;
    const unsigned mb_l0 = mb_hi + 8;
    const unsigned mb_l1 = mb_hi + 16;

    if (tid == 0) {
        asm volatile("mbarrier.init.shared.b64 [%0], 1;" :: "r"(mb_hi) : "memory");
        asm volatile("mbarrier.init.shared.b64 [%0], 1;" :: "r"(mb_l0) : "memory");
        asm volatile("mbarrier.init.shared.b64 [%0], 1;" :: "r"(mb_l1) : "memory");
        asm volatile("fence.proxy.async.shared::cta;" ::: "memory");
    }

    const float* Bb = B + (n * 160) * 4096 + hw;
    const unsigned long long Wg =
        (unsigned long long)__cvta_generic_to_global(g_W16);

    float acc[64];
    #pragma unroll
    for (int i = 0; i < 64; ++i) acc[i] = 0.f;

    const char* gl = smem_raw + (lane & 7) * 16;    // lane's 16B d-slice base
    const int px_sub = lane >> 3;                    // 0..3

    // hi-fill: rows [448,1024) of fern f -> OFF_HI (72KB)
    auto issue_fill_hi = [&](int f) {
        asm volatile("mbarrier.arrive.expect_tx.shared.b64 _, [%0], %1;"
                     :: "r"(mb_hi), "r"(HISZ) : "memory");
        unsigned long long src = Wg + (unsigned long long)f * 131072ull + LOSZ;
        #pragma unroll
        for (int c = 0; c < 2; ++c) {
            asm volatile(
                "cp.async.bulk.shared::cta.global.mbarrier::complete_tx::bytes "
                "[%0], [%1], %2, [%3];"
                :: "r"(smem_u32 + OFF_HI + c * 36864), "l"(src + c * 36864ull),
                   "r"(36864), "r"(mb_hi) : "memory");
        }
    };
    // lo-fill: rows [0,448) of fern f -> lo buffer b (56KB)
    auto issue_fill_lo = [&](int f, int b) {
        const unsigned mb = b ? mb_l1 : mb_l0;
        const unsigned dst = smem_u32 + (b ? OFF_L1 : OFF_L0);
        asm volatile("mbarrier.arrive.expect_tx.shared.b64 _, [%0], %1;"
                     :: "r"(mb), "r"(LOSZ) : "memory");
        unsigned long long src = Wg + (unsigned long long)f * 131072ull;
        #pragma unroll
        for (int c = 0; c < 2; ++c) {
            asm volatile(
                "cp.async.bulk.shared::cta.global.mbarrier::complete_tx::bytes "
                "[%0], [%1], %2, [%3];"
                :: "r"(dst + c * 28672), "l"(src + c * 28672ull),
                   "r"(28672), "r"(mb) : "memory");
        }
    };

    // phase-1: fern logic -> params with RESOLVED smem offsets (lo_add = consuming
    // fern's lo-buffer base). 8 selects here replace 64 in phase-2.
    auto phase1 = [&](const float* tv, int lo_add) {
        int wb = 0;
        float bsp = 1.f;
        #pragma unroll
        for (int k = 0; k < 10; ++k) {
            if (tv[k] >= 0.5f) wb |= (1 << k);
            bsp *= fmaxf(tv[k], 1.f - tv[k]);
        }
        int abi0, abi1, abi2;
        float av0, av1, av2;
        {
            float best = fabsf(tv[0] - 0.5f); int bi = 0; float bt = tv[0];
            #pragma unroll
            for (int k = 1; k < 10; ++k) {
                float ak = fabsf(tv[k] - 0.5f);
                if (ak < best) { best = ak; bi = k; bt = tv[k]; }
            }
            abi0 = bi; av0 = bt;
        }
        {
            float best = 3.0e38f; int bi = 0; float bt = 0.f;
            #pragma unroll
            for (int k = 0; k < 10; ++k) {
                float ak = fabsf(tv[k] - 0.5f);
                if (k != abi0 && ak < best) { best = ak; bi = k; bt = tv[k]; }
            }
            abi1 = bi; av1 = bt;
        }
        {
            float best = 3.0e38f; int bi = 0; float bt = 0.f;
            #pragma unroll
            for (int k = 0; k < 10; ++k) {
                float ak = fabsf(tv[k] - 0.5f);
                if (k != abi0 && k != abi1 && ak < best) { best = ak; bi = k; bt = tv[k]; }
            }
            abi2 = bi; av2 = bt;
        }

        const float d0 = 1.f - av0, d1 = 1.f - av1, d2 = 1.f - av2;
        const float denom = fmaxf(av0, d0) * fmaxf(av1, d1) * fmaxf(av2, d2);
        const float bspp = valid ? (bsp / denom) : 0.f;

        float cp[8];
        {
            float g0 = bspp * d0,  g1 = bspp * av0;
            float c00 = g0 * d1,  c10 = g1 * d1;
            float c01 = g0 * av1, c11 = g1 * av1;
            cp[0] = c00 * d2;  cp[1] = c10 * d2;  cp[2] = c01 * d2;  cp[3] = c11 * d2;
            cp[4] = c00 * av2; cp[5] = c10 * av2; cp[6] = c01 * av2; cp[7] = c11 * av2;
        }
        unsigned ch[8];
        #pragma unroll
        for (int j = 0; j < 8; ++j) {
            __half2 hh = __floats2half2_rn(cp[j], cp[j]);
            ch[j] = *reinterpret_cast<unsigned*>(&hh);
        }
        int io[8];
        {
            const int m0 = 1 << abi0, m1 = 1 << abi1, m2 = 1 << abi2;
            const int b0 = wb & ~(m0 | m1 | m2);
            const int i0 = b0, i1 = b0 | m0, i2 = b0 | m1, i3 = b0 | m0 | m1;
            io[0] = i0 << 7;        io[1] = i1 << 7;
            io[2] = i2 << 7;        io[3] = i3 << 7;
            io[4] = (i0 | m2) << 7; io[5] = (i1 | m2) << 7;
            io[6] = (i2 | m2) << 7; io[7] = (i3 | m2) << 7;
        }
        // resolve lo/hi placement now (consumer's buffer layout)
        #pragma unroll
        for (int j = 0; j < 8; ++j)
            io[j] = (io[j] < LOSZ) ? (io[j] + lo_add) : (io[j] - LOSZ + OFF_HI);

        uint4* myp = (uint4*)(s_par + tid * PAR_STRIDE);
        #pragma unroll
        for (int jj = 0; jj < 4; ++jj)
            myp[jj] = make_uint4(ch[2*jj], (unsigned)io[2*jj],
                                 ch[2*jj+1], (unsigned)io[2*jj+1]);
        __syncwarp();
    };

    // ---- prologue: B for ferns 0,1; phase1(0, buf0); prime fills ----
    float tc[10], tn[10];
    #pragma unroll
    for (int k = 0; k < 10; ++k) tc[k] = Bb[k * 4096];
    #pragma unroll
    for (int k = 0; k < 10; ++k) tn[k] = Bb[40960 + k * 4096];
    phase1(tc, OFF_L0);
    __syncthreads();            // mbar init visible before any wait
    if (tid == 0) {
        issue_fill_lo(0, 0);
        issue_fill_hi(0);
        issue_fill_lo(1, 1);
    }

    #pragma unroll 1
    for (int m = 0; m < 16; ++m) {
        mbar_wait(mb_hi, (unsigned)(m & 1));
        mbar_wait((m & 1) ? mb_l1 : mb_l0, (unsigned)((m >> 1) & 1));

        // ---- phase 2: v6-identical HFMA2 gathers (offsets pre-resolved) ----
        #pragma unroll
        for (int g = 0; g < 8; ++g) {
            if (g * 4 < rem) {                    // warp-uniform guard
                const uint4* pp =
                    (const uint4*)(s_par + (warp * 32 + g * 4 + px_sub) * PAR_STRIDE);
                __half2 h0 = __floats2half2_rn(0.f, 0.f);
                __half2 h1 = h0, h2 = h0, h3 = h0;
                #pragma unroll
                for (int jj = 0; jj < 4; ++jj) {
                    uint4 pr = pp[jj];
                    {
                        __half2 c = u2h2(pr.x);
                        uint4 w4 = *(const uint4*)(gl + pr.y);
                        h0 = __hfma2(c, u2h2(w4.x), h0);
                        h1 = __hfma2(c, u2h2(w4.y), h1);
                        h2 = __hfma2(c, u2h2(w4.z), h2);
                        h3 = __hfma2(c, u2h2(w4.w), h3);
                    }
                    {
                        __half2 c = u2h2(pr.z);
                        uint4 w4 = *(const uint4*)(gl + pr.w);
                        h0 = __hfma2(c, u2h2(w4.x), h0);
                        h1 = __hfma2(c, u2h2(w4.y), h1);
                        h2 = __hfma2(c, u2h2(w4.z), h2);
                        h3 = __hfma2(c, u2h2(w4.w), h3);
                    }
                }
                float2 f0 = __half22float2(h0);
                float2 f1 = __half22float2(h1);
                float2 f2 = __half22float2(h2);
                float2 f3 = __half22float2(h3);
                acc[g*8+0] += f0.x; acc[g*8+1] += f0.y;
                acc[g*8+2] += f1.x; acc[g*8+3] += f1.y;
                acc[g*8+4] += f2.x; acc[g*8+5] += f2.y;
                acc[g*8+6] += f3.x; acc[g*8+7] += f3.y;
            }
        }

        if (m < 15) {
            // gate: all warps done with fern m's table regions
            if (warp == 0) {
                asm volatile("bar.sync 1, 512;" ::: "memory");
                if (tid == 0) {
                    issue_fill_hi(m + 1);                       // exposed next iter
                    if (m < 14) issue_fill_lo(m + 2, m & 1);    // overlaps next iter
                }
            } else {
                asm volatile("bar.arrive 1, 512;" ::: "memory");
            }

            // prefetch B for fern m+2
            float t2[10];
            {
                const int mn = (m + 2 < 16) ? (m + 2) : 15;
                const float* pf = Bb + mn * 40960;
                #pragma unroll
                for (int k = 0; k < 10; ++k) t2[k] = pf[k * 4096];
            }

            phase1(tn, ((m + 1) & 1) ? OFF_L1 : OFF_L0);   // fern m+1 params

            #pragma unroll
            for (int k = 0; k < 10; ++k) tn[k] = t2[k];
        }
    }

    // ---- epilogue: stride-65 transpose -> coalesced stores ----
    __syncthreads();
    #pragma unroll
    for (int g = 0; g < 8; ++g) {
        int pxl = warp * 32 + g * 4 + px_sub;
        float* row = s_out + pxl * 65 + (lane & 7) * 8;
        #pragma unroll
        for (int r = 0; r < 8; ++r) row[r] = acc[g * 8 + r];
    }
    __syncthreads();

    if (valid) {
        const float* srow = s_out + tid * 65;
        float* obase = out + (n * 64) * 4096 + hw;
        #pragma unroll
        for (int d = 0; d < 64; ++d)
            obase[d * 4096] = srow[d] + bias[d];
    }
}

extern "C" void kernel_launch(void* const* d_in, const int* in_sizes, int n_in,
                              void* d_out, int out_size)
{
    const float* B    = (const float*)d_in[0];
    const float* W    = (const float*)d_in[1];
    const float* bias = (const float*)d_in[2];
    float* out = (float*)d_out;

    cvt_kernel<<<1024, 256>>>((const float4*)W);

    cudaFuncSetAttribute(fern_kernel, cudaFuncAttributeMaxDynamicSharedMemorySize, SMEM_BYTES);
    fern_kernel<<<NCTA, TPB, SMEM_BYTES>>>(B, bias, out);
}